// round 1
// baseline (speedup 1.0000x reference)
#include <cuda_runtime.h>

#define L_SEQ 512
#define T_TAGS 64
#define WARPS 4
#define BPW 2   // batches per warp

// runtime tag-dtype detection flag (0 -> tags are int64, 1 -> int32)
__device__ int g_odd_nonzero;

__global__ void k_flag_init() {
    if (threadIdx.x == 0) g_odd_nonzero = 0;
}

// If tags are int64 (little-endian, values 0..63), every odd 32-bit word is 0.
// If int32, odd words are random tags in [0,64) -> all-zero over 8192 samples
// has probability (1/64)^8192 ~ 0.
__global__ void k_detect(const unsigned int* __restrict__ tw) {
    int i = blockIdx.x * blockDim.x + threadIdx.x;   // 0..8191
    if (tw[2 * i + 1] != 0u) g_odd_nonzero = 1;
}

__device__ __forceinline__ unsigned long long bcast2(float x) {
    unsigned long long r;
    asm("mov.b64 %0, {%1, %1};" : "=l"(r) : "f"(x));
    return r;
}
#define FMA2(d, a, b) asm("fma.rn.f32x2 %0, %1, %2, %0;" : "+l"(d) : "l"(a), "l"(b))

__global__ __launch_bounds__(128)
void crf_kernel(const float* __restrict__ logits,
                const unsigned int* __restrict__ tagw,
                const int* __restrict__ mask,
                const float* __restrict__ trans,
                float* __restrict__ out)
{
    __shared__ float expT_s[64 * 64];
    __shared__ float trans_s[64 * 64];
    __shared__ float pbuf[WARPS][BPW][68];   // 68: bank-offset padding between batch halves

    const int tid = threadIdx.x;
    for (int i = tid; i < 4096; i += 128) {
        float t = trans[i];
        trans_s[i] = t;
        expT_s[i] = __expf(t);
    }
    __syncthreads();

    const int w = tid >> 5, lane = tid & 31;
    const int b_sub = lane >> 4;          // which batch of the pair
    const int jl = lane & 15;             // j-lane within group
    const int j0 = jl << 2;               // 4 consecutive tags per lane
    const int b = (blockIdx.x * WARPS + w) * BPW + b_sub;
    const int is64 = (g_odd_nonzero == 0) ? 1 : 0;

    const float* lg = logits + (size_t)b * (L_SEQ * T_TAGS);
    const int mbase = b * L_SEQ;

    // ---- l = 0 ----
    float4 a0 = *(const float4*)(lg + j0);
    float al0 = a0.x, al1 = a0.y, al2 = a0.z, al3 = a0.w;

    int idx0 = mbase;
    int t0 = (int)tagw[is64 ? (idx0 << 1) : idx0];
    float gold = 0.f;
    {
        float m0 = (float)mask[mbase];
        if (jl == (t0 >> 2)) {
            int c = t0 & 3;
            float ev = a0.x;
            ev = (c == 1) ? a0.y : ev;
            ev = (c == 2) ? a0.z : ev;
            ev = (c == 3) ? a0.w : ev;
            gold = ev * m0;
        }
    }
    int tprev = t0;

    // current-step operands (l = 1), prefetched
    float4 cem = *(const float4*)(lg + T_TAGS + j0);
    int cm = mask[mbase + 1];
    int idx1 = mbase + 1;
    int ct = (int)tagw[is64 ? (idx1 << 1) : idx1];

    for (int l = 1; l < L_SEQ; ++l) {
        // depth-1 software prefetch of next step's operands
        float4 nem = cem;
        int nm = 0, nt = 0;
        if (l + 1 < L_SEQ) {
            nem = *(const float4*)(lg + (l + 1) * T_TAGS + j0);
            nm = mask[mbase + l + 1];
            int idx = mbase + l + 1;
            nt = (int)tagw[is64 ? (idx << 1) : idx];
        }

        // ---- max over the 64 alphas of this batch (16-lane group) ----
        float mx = fmaxf(fmaxf(al0, al1), fmaxf(al2, al3));
        mx = fmaxf(mx, __shfl_xor_sync(0xffffffffu, mx, 1));
        mx = fmaxf(mx, __shfl_xor_sync(0xffffffffu, mx, 2));
        mx = fmaxf(mx, __shfl_xor_sync(0xffffffffu, mx, 4));
        mx = fmaxf(mx, __shfl_xor_sync(0xffffffffu, mx, 8));

        // ---- p = exp(alpha - mx), stage in smem for broadcast ----
        float4 pv;
        pv.x = __expf(al0 - mx);
        pv.y = __expf(al1 - mx);
        pv.z = __expf(al2 - mx);
        pv.w = __expf(al3 - mx);
        *(float4*)&pbuf[w][b_sub][j0] = pv;
        __syncwarp();

        // ---- s[j] = sum_i p[i] * expT[i][j], packed f32x2 FMAs ----
        unsigned long long s01 = 0ull, s23 = 0ull;
        #pragma unroll
        for (int i = 0; i < 64; i += 4) {
            float4 pq = *(const float4*)&pbuf[w][b_sub][i];
            #pragma unroll
            for (int k = 0; k < 4; ++k) {
                float pk = (k == 0) ? pq.x : (k == 1) ? pq.y : (k == 2) ? pq.z : pq.w;
                unsigned long long pp = bcast2(pk);
                ulonglong2 e = *(const ulonglong2*)&expT_s[(i + k) * 64 + j0];
                FMA2(s01, pp, e.x);
                FMA2(s23, pp, e.y);
            }
        }
        __syncwarp();   // protect pbuf before next iteration's store

        float s0, s1, s2, s3;
        asm("mov.b64 {%0, %1}, %2;" : "=f"(s0), "=f"(s1) : "l"(s01));
        asm("mov.b64 {%0, %1}, %2;" : "=f"(s2), "=f"(s3) : "l"(s23));

        float n0 = mx + __logf(s0) + cem.x;
        float n1 = mx + __logf(s1) + cem.y;
        float n2 = mx + __logf(s2) + cem.z;
        float n3 = mx + __logf(s3) + cem.w;

        bool keep = cm > 0;
        al0 = keep ? n0 : al0;
        al1 = keep ? n1 : al1;
        al2 = keep ? n2 : al2;
        al3 = keep ? n3 : al3;

        // ---- gold score accumulation ----
        float lm = (float)cm;
        if (jl == (ct >> 2)) {
            int c = ct & 3;
            float ev = cem.x;
            ev = (c == 1) ? cem.y : ev;
            ev = (c == 2) ? cem.z : ev;
            ev = (c == 3) ? cem.w : ev;
            gold += ev * lm;
        }
        if (jl == 0) gold += trans_s[tprev * 64 + ct] * lm;
        tprev = ct;

        cem = nem; cm = nm; ct = nt;
    }

    // ---- final logsumexp over alpha + group reductions ----
    float mx = fmaxf(fmaxf(al0, al1), fmaxf(al2, al3));
    mx = fmaxf(mx, __shfl_xor_sync(0xffffffffu, mx, 1));
    mx = fmaxf(mx, __shfl_xor_sync(0xffffffffu, mx, 2));
    mx = fmaxf(mx, __shfl_xor_sync(0xffffffffu, mx, 4));
    mx = fmaxf(mx, __shfl_xor_sync(0xffffffffu, mx, 8));

    float s = __expf(al0 - mx) + __expf(al1 - mx) + __expf(al2 - mx) + __expf(al3 - mx);
    s += __shfl_xor_sync(0xffffffffu, s, 1);
    s += __shfl_xor_sync(0xffffffffu, s, 2);
    s += __shfl_xor_sync(0xffffffffu, s, 4);
    s += __shfl_xor_sync(0xffffffffu, s, 8);

    gold += __shfl_xor_sync(0xffffffffu, gold, 1);
    gold += __shfl_xor_sync(0xffffffffu, gold, 2);
    gold += __shfl_xor_sync(0xffffffffu, gold, 4);
    gold += __shfl_xor_sync(0xffffffffu, gold, 8);

    if (jl == 0) out[b] = (mx + __logf(s)) - gold;
}

extern "C" void kernel_launch(void* const* d_in, const int* in_sizes, int n_in,
                              void* d_out, int out_size)
{
    const float*        logits = (const float*)d_in[0];
    const unsigned int* tagw   = (const unsigned int*)d_in[1];
    const int*          mask   = (const int*)d_in[2];
    const float*        trans  = (const float*)d_in[3];
    float*              out    = (float*)d_out;

    k_flag_init<<<1, 32>>>();
    k_detect<<<32, 256>>>(tagw);
    crf_kernel<<<128, 128>>>(logits, tagw, mask, trans, out);
}